// round 15
// baseline (speedup 1.0000x reference)
#include <cuda_runtime.h>
#include <cuda_bf16.h>
#include <cuda_fp16.h>
#include <cstdint>

// ---------------- problem constants ----------------
#define Bsz 64
#define Nn  4096
#define Ee  8192
#define MROWS (Bsz * Nn)        // 262144
#define PCOLS 768               // [W1top(256) | W1bot(256) | A1top(128) | A1bot(128)]
#define KDIM  256
#define NEDGE (Bsz * Ee)        // 524288

// ---------------- scratch (__device__ globals; no allocs allowed) ----------
__device__ __align__(16) float    g_P[(size_t)MROWS * PCOLS];   // partials fp32 (805 MB)
__device__ __align__(16) __half   g_Ahf[(size_t)MROWS * 512];   // [m][0:256)=hi, [256:512)=lo
__device__ __align__(16) __half   g_B2[(size_t)PCOLS * 256];    // [n][k] = fp16(Wcat[k][n])
__device__ __align__(16) uint32_t g_A2Th[64 * 64];              // A2^T hi (bf16 pairs)
__device__ __align__(16) uint32_t g_A2Tl[64 * 64];              // A2^T lo

// ---------------- helpers ----------------
__device__ __forceinline__ uint32_t smem_u32(const void* p) {
    uint32_t a;
    asm("{ .reg .u64 t; cvta.to.shared.u64 t, %1; cvt.u32.u64 %0, t; }" : "=r"(a) : "l"(p));
    return a;
}
__device__ __forceinline__ void cp16(uint32_t dst, const void* src) {
    asm volatile("cp.async.cg.shared.global [%0], [%1], 16;" :: "r"(dst), "l"(src));
}
#define CP_COMMIT() asm volatile("cp.async.commit_group;" ::: "memory")
#define CP_WAIT(n)  asm volatile("cp.async.wait_group %0;" :: "n"(n) : "memory")

__device__ __forceinline__ void mma_f16(float* c,
    uint32_t a0, uint32_t a1, uint32_t a2, uint32_t a3, uint32_t b0, uint32_t b1) {
    asm volatile(
        "mma.sync.aligned.m16n8k16.row.col.f32.f16.f16.f32 "
        "{%0,%1,%2,%3}, {%4,%5,%6,%7}, {%8,%9}, {%0,%1,%2,%3};"
        : "+f"(c[0]), "+f"(c[1]), "+f"(c[2]), "+f"(c[3])
        : "r"(a0), "r"(a1), "r"(a2), "r"(a3), "r"(b0), "r"(b1));
}
__device__ __forceinline__ void mma_bf16(float* c,
    uint32_t a0, uint32_t a1, uint32_t a2, uint32_t a3, uint32_t b0, uint32_t b1) {
    asm volatile(
        "mma.sync.aligned.m16n8k16.row.col.f32.bf16.bf16.f32 "
        "{%0,%1,%2,%3}, {%4,%5,%6,%7}, {%8,%9}, {%0,%1,%2,%3};"
        : "+f"(c[0]), "+f"(c[1]), "+f"(c[2]), "+f"(c[3])
        : "r"(a0), "r"(a1), "r"(a2), "r"(a3), "r"(b0), "r"(b1));
}
__device__ __forceinline__ void ldsm_x4(uint32_t* r, uint32_t addr) {
    asm volatile("ldmatrix.sync.aligned.m8n8.x4.shared.b16 {%0,%1,%2,%3}, [%4];"
        : "=r"(r[0]), "=r"(r[1]), "=r"(r[2]), "=r"(r[3]) : "r"(addr));
}
__device__ __forceinline__ uint32_t pack_bf16(float lo, float hi) {
    __nv_bfloat162 t = __floats2bfloat162_rn(lo, hi);
    return *reinterpret_cast<uint32_t*>(&t);
}

// ---------------------------------------------------------------------------
// prep_a: split node embeddings into fp16 hi/lo.
// ---------------------------------------------------------------------------
__global__ __launch_bounds__(256) void prep_a_kernel(const float* __restrict__ node) {
    int i = blockIdx.x * blockDim.x + threadIdx.x;
    if (i >= MROWS * 64) return;
    int m  = i >> 6;
    int kq = (i & 63) * 4;
    float4 v = *reinterpret_cast<const float4*>(node + (size_t)m * 256 + kq);
    __half h[4], l[4];
    float vv[4] = {v.x, v.y, v.z, v.w};
    #pragma unroll
    for (int j = 0; j < 4; j++) {
        h[j] = __float2half_rn(vv[j]);
        l[j] = __float2half_rn(vv[j] - __half2float(h[j]));
    }
    *reinterpret_cast<uint2*>(&g_Ahf[(size_t)m * 512 + kq])       = *reinterpret_cast<uint2*>(h);
    *reinterpret_cast<uint2*>(&g_Ahf[(size_t)m * 512 + 256 + kq]) = *reinterpret_cast<uint2*>(l);
}

// ---------------------------------------------------------------------------
// prep_w: g_B2[n][k] = fp16(Wcat[k][n])
// ---------------------------------------------------------------------------
__global__ __launch_bounds__(256) void prep_w_kernel(const float* __restrict__ W1,
                                                     const float* __restrict__ A1) {
    int i = blockIdx.x * blockDim.x + threadIdx.x;
    if (i >= PCOLS * 256) return;
    int n = i >> 8;
    int k = i & 255;
    float v;
    if (n < 256)        v = W1[k * 256 + n];
    else if (n < 512)   v = W1[(256 + k) * 256 + (n - 256)];
    else if (n < 640)   v = A1[k * 128 + (n - 512)];
    else                v = A1[(256 + k) * 128 + (n - 640)];
    g_B2[i] = __float2half_rn(v);
}

// ---------------------------------------------------------------------------
// prep_a2: A2^T hi/lo bf16 u32-packed fragments (edge matvec).
// ---------------------------------------------------------------------------
__global__ __launch_bounds__(256) void prep_a2_kernel(const float* __restrict__ A2) {
    int i = blockIdx.x * blockDim.x + threadIdx.x;
    if (i >= 64 * 64) return;
    int n  = i >> 6;
    int kk = i & 63;
    float v0 = A2[(2 * kk)     * 64 + n];
    float v1 = A2[(2 * kk + 1) * 64 + n];
    float h0 = __bfloat162float(__float2bfloat16_rn(v0));
    float h1 = __bfloat162float(__float2bfloat16_rn(v1));
    g_A2Th[i] = pack_bf16(h0, h1);
    g_A2Tl[i] = pack_bf16(v0 - h0, v1 - h1);
}

// ---------------------------------------------------------------------------
// GEMM: g_P = [Ah|Al] @ [Bh;Bh] (fp16 2-term, f32 acc), K2 = 512.
// CTA tile 128M x 256N, 8 warps of 64x64 (2x4), BK=64 (8 iters),
// 3-stage cp.async pipeline, ldmatrix x4 for A and B. 1 CTA/SM.
// ---------------------------------------------------------------------------
#define BK 64
#define AST 72                           // smem row stride in halves
#define A_ROWS 128
#define B_ROWS 256
#define STAGE_H ((A_ROWS + B_ROWS) * AST)     // halves per stage
#define STAGE_B (STAGE_H * 2)                 // 55296 bytes
#define GEMM_SMEM (3 * STAGE_B)               // 165888
#define KITERS 8

__global__ __launch_bounds__(256, 1) void gemm_kernel() {
    extern __shared__ __align__(16) __half dyn[];
    const uint32_t sb = smem_u32(dyn);

    const int tid  = threadIdx.x;
    const int wid  = tid >> 5, lane = tid & 31;
    const int g    = lane >> 2, tig = lane & 3;
    const int warp_m = (wid & 1) * 64;        // 0 / 64
    const int warp_n = (wid >> 1) * 64;       // 0,64,128,192
    const int n0 = blockIdx.x * 256;          // 0..512
    const int m0 = blockIdx.y * 128;

    float acc[4][8][4];
    #pragma unroll
    for (int i = 0; i < 4; i++)
        #pragma unroll
        for (int j = 0; j < 8; j++)
            #pragma unroll
            for (int q = 0; q < 4; q++) acc[i][j][q] = 0.0f;

    auto load_stage = [&](int ks, int buf) {
        const int seg  = ks >> 2;                       // 0: Ah, 1: Al
        const int a_k0 = seg * 256 + (ks & 3) * BK;
        const int b_k0 = (ks & 3) * BK;                 // Bh reused across segments
        const uint32_t da = sb + (uint32_t)buf * STAGE_B;
        const uint32_t db = da + A_ROWS * AST * 2;
        #pragma unroll
        for (int h = 0; h < 12; h++) {
            int id = tid + h * 256;                     // 0..3071
            int r  = id >> 3, p = id & 7;               // r 0..383
            if (r < A_ROWS) {
                cp16(da + (uint32_t)(r * AST + p * 8) * 2,
                     &g_Ahf[(size_t)(m0 + r) * 512 + a_k0 + p * 8]);
            } else {
                int rb = r - A_ROWS;
                cp16(db + (uint32_t)(rb * AST + p * 8) * 2,
                     &g_B2[(size_t)(n0 + rb) * 256 + b_k0 + p * 8]);
            }
        }
    };

    const int a_row  = lane & 15;
    const int a_k8   = ((lane >> 4) & 1) * 8;
    const int b_rowp = (lane & 7) + ((lane >> 4) & 1) * 8;
    const int b_k8p  = ((lane >> 3) & 1) * 8;

    load_stage(0, 0); CP_COMMIT();
    load_stage(1, 1); CP_COMMIT();

    for (int ks = 0; ks < KITERS; ks++) {
        if (ks < KITERS - 2) { CP_WAIT(1); } else { CP_WAIT(0); }
        __syncthreads();

        const uint32_t aB = sb + (uint32_t)(ks % 3) * STAGE_B;
        const uint32_t bB = aB + A_ROWS * AST * 2;

        #pragma unroll
        for (int ksel = 0; ksel < 4; ksel++) {
            uint32_t a[4][4], b[8][2];
            #pragma unroll
            for (int mi = 0; mi < 4; mi++) {
                int row = warp_m + mi * 16 + a_row;
                ldsm_x4(a[mi], aB + (uint32_t)(row * AST + ksel * 16 + a_k8) * 2);
            }
            #pragma unroll
            for (int njp = 0; njp < 4; njp++) {
                int row = warp_n + njp * 16 + b_rowp;
                uint32_t r4[4];
                ldsm_x4(r4, bB + (uint32_t)(row * AST + ksel * 16 + b_k8p) * 2);
                b[2 * njp][0]     = r4[0]; b[2 * njp][1]     = r4[1];
                b[2 * njp + 1][0] = r4[2]; b[2 * njp + 1][1] = r4[3];
            }
            #pragma unroll
            for (int mi = 0; mi < 4; mi++)
                #pragma unroll
                for (int nj = 0; nj < 8; nj++)
                    mma_f16(acc[mi][nj], a[mi][0], a[mi][1], a[mi][2], a[mi][3],
                            b[nj][0], b[nj][1]);
        }

        if (ks + 2 < KITERS) { load_stage(ks + 2, (ks + 2) % 3); CP_COMMIT(); }
    }

    #pragma unroll
    for (int mi = 0; mi < 4; mi++) {
        #pragma unroll
        for (int nj = 0; nj < 8; nj++) {
            int row = m0 + warp_m + mi * 16 + g;
            int col = n0 + warp_n + nj * 8 + 2 * tig;
            *reinterpret_cast<float2*>(&g_P[(size_t)row * PCOLS + col]) =
                make_float2(acc[mi][nj][0], acc[mi][nj][1]);
            *reinterpret_cast<float2*>(&g_P[(size_t)(row + 8) * PCOLS + col]) =
                make_float2(acc[mi][nj][2], acc[mi][nj][3]);
        }
    }
}

// ---------------------------------------------------------------------------
// Edge kernel (R14 best, unchanged): warp-batched 16 edges/tile.
// ---------------------------------------------------------------------------
#define EW 4
#define NTILES (NEDGE / 16)      // 32768
#define EDGE_GRID 1184

__global__ __launch_bounds__(128) void edge_kernel(
    const float* __restrict__ army, const int* __restrict__ edges,
    const float* __restrict__ b1, const float* __restrict__ W2, const float* __restrict__ b2,
    const float* __restrict__ a1, const float* __restrict__ a2,
    float* __restrict__ out_edge, float* __restrict__ out_army)
{
    __shared__ uint32_t stg_h[EW][16 * 64];
    __shared__ uint32_t stg_l[EW][16 * 64];
    __shared__ float b1s[256], W2s[256], a1s[128];
    __shared__ float srcAs[EW][16];

    const int tid = threadIdx.x, w = tid >> 5, lane = tid & 31;
    const int grp = lane >> 2, tig = lane & 3;

    b1s[tid] = b1[tid];       b1s[tid + 128] = b1[tid + 128];
    W2s[tid] = W2[tid];       W2s[tid + 128] = W2[tid + 128];
    a1s[tid] = a1[tid];
    const float b2v = b2[0];

    float2 a2g[8];
    #pragma unroll
    for (int nj = 0; nj < 8; nj++) {
        int m = nj * 8 + 2 * tig;
        a2g[nj] = make_float2(a2[m], a2[m + 1]);
    }
    __syncthreads();

    for (int tile = blockIdx.x * EW + w; tile < NTILES; tile += EDGE_GRID * EW) {
        const int e0 = tile * 16;

        #pragma unroll 2
        for (int e = 0; e < 16; e++) {
            const int eidx = e0 + e;
            const int b = eidx >> 13;
            const int src = edges[2 * eidx], tgt = edges[2 * eidx + 1];
            const int sc = min(max(src, 0), Nn - 1);
            const int tc = min(max(tgt, 0), Nn - 1);
            const float* Ps = g_P + ((size_t)(b << 12) + sc) * PCOLS;
            const float* Pt = g_P + ((size_t)(b << 12) + tc) * PCOLS;

            float ep = 0.0f;
            #pragma unroll
            for (int q = 0; q < 2; q++) {
                int f = lane + 32 * q;
                float4 ps = *reinterpret_cast<const float4*>(Ps + 4 * f);
                float4 pt = *reinterpret_cast<const float4*>(Pt + 256 + 4 * f);
                float4 bb = *reinterpret_cast<const float4*>(b1s + 4 * f);
                float4 ww = *reinterpret_cast<const float4*>(W2s + 4 * f);
                ep += fmaxf(ps.x + pt.x + bb.x, 0.0f) * ww.x;
                ep += fmaxf(ps.y + pt.y + bb.y, 0.0f) * ww.y;
                ep += fmaxf(ps.z + pt.z + bb.z, 0.0f) * ww.z;
                ep += fmaxf(ps.w + pt.w + bb.w, 0.0f) * ww.w;
            }
            #pragma unroll
            for (int o = 16; o; o >>= 1) ep += __shfl_xor_sync(0xffffffffu, ep, o);

            {
                float4 ps = *reinterpret_cast<const float4*>(Ps + 512 + 4 * lane);
                float4 pt = *reinterpret_cast<const float4*>(Pt + 640 + 4 * lane);
                float4 aa = *reinterpret_cast<const float4*>(a1s + 4 * lane);
                float g0 = fmaxf(ps.x + pt.x + aa.x, 0.0f);
                float g1 = fmaxf(ps.y + pt.y + aa.y, 0.0f);
                float g2 = fmaxf(ps.z + pt.z + aa.z, 0.0f);
                float g3 = fmaxf(ps.w + pt.w + aa.w, 0.0f);
                float h0 = __bfloat162float(__float2bfloat16_rn(g0));
                float h1 = __bfloat162float(__float2bfloat16_rn(g1));
                float h2 = __bfloat162float(__float2bfloat16_rn(g2));
                float h3 = __bfloat162float(__float2bfloat16_rn(g3));
                const uint32_t sw = 4u * (e & 7);
                const uint32_t o0 = (uint32_t)(e * 64) + ((2u * lane)     ^ sw);
                const uint32_t o1 = (uint32_t)(e * 64) + ((2u * lane + 1) ^ sw);
                stg_h[w][o0] = pack_bf16(h0, h1);
                stg_h[w][o1] = pack_bf16(h2, h3);
                stg_l[w][o0] = pack_bf16(g0 - h0, g1 - h1);
                stg_l[w][o1] = pack_bf16(g2 - h2, g3 - h3);
            }

            const float srcA = army[(b << 12) + sc];
            const float tgtA = army[(b << 12) + tc];
            if (lane == 0) {
                float el = ep + b2v;
                bool valid = (src >= 0) && (tgt >= 0);
                if (valid && ((srcA <= 2.0f) || (tgtA >= 3.0f * srcA))) el -= 1.0f;
                if (valid && (src == tgt))                              el -= 100.0f;
                out_edge[eidx] = el;
                srcAs[w][e] = srcA;
            }
        }
        __syncwarp();

        float acc[8][4];
        #pragma unroll
        for (int nj = 0; nj < 8; nj++)
            #pragma unroll
            for (int q = 0; q < 4; q++) acc[nj][q] = 0.0f;

        const uint32_t swg = 4u * grp;
        #pragma unroll
        for (int ks = 0; ks < 8; ks++) {
            const uint32_t kb = 8u * ks;
            uint32_t ah0 = stg_h[w][grp * 64       + ((kb + tig)     ^ swg)];
            uint32_t ah1 = stg_h[w][(grp + 8) * 64 + ((kb + tig)     ^ swg)];
            uint32_t ah2 = stg_h[w][grp * 64       + ((kb + 4 + tig) ^ swg)];
            uint32_t ah3 = stg_h[w][(grp + 8) * 64 + ((kb + 4 + tig) ^ swg)];
            uint32_t al0 = stg_l[w][grp * 64       + ((kb + tig)     ^ swg)];
            uint32_t al1 = stg_l[w][(grp + 8) * 64 + ((kb + tig)     ^ swg)];
            uint32_t al2 = stg_l[w][grp * 64       + ((kb + 4 + tig) ^ swg)];
            uint32_t al3 = stg_l[w][(grp + 8) * 64 + ((kb + 4 + tig) ^ swg)];
            #pragma unroll
            for (int nj = 0; nj < 8; nj++) {
                const int bi = (nj * 8 + grp) * 64 + kb + tig;
                uint32_t bh0 = g_A2Th[bi], bh1 = g_A2Th[bi + 4];
                uint32_t bl0 = g_A2Tl[bi], bl1 = g_A2Tl[bi + 4];
                mma_bf16(acc[nj], ah0, ah1, ah2, ah3, bh0, bh1);
                mma_bf16(acc[nj], ah0, ah1, ah2, ah3, bl0, bl1);
                mma_bf16(acc[nj], al0, al1, al2, al3, bh0, bh1);
            }
        }

        const float mS0 = srcAs[w][grp] - 1.0f;
        const float mS1 = srcAs[w][grp + 8] - 1.0f;
        float* o0 = out_army + (size_t)(e0 + grp) * 64;
        float* o1 = out_army + (size_t)(e0 + grp + 8) * 64;
        #pragma unroll
        for (int nj = 0; nj < 8; nj++) {
            const int m = nj * 8 + 2 * tig;
            const float fm0 = (float)m, fm1 = (float)(m + 1);
            float v0 = (fm0 <= mS0) ? acc[nj][0] + a2g[nj].x : -1e9f;
            float v1 = (fm1 <= mS0) ? acc[nj][1] + a2g[nj].y : -1e9f;
            float v2 = (fm0 <= mS1) ? acc[nj][2] + a2g[nj].x : -1e9f;
            float v3 = (fm1 <= mS1) ? acc[nj][3] + a2g[nj].y : -1e9f;
            *reinterpret_cast<float2*>(o0 + m) = make_float2(v0, v1);
            *reinterpret_cast<float2*>(o1 + m) = make_float2(v2, v3);
        }
        __syncwarp();
    }
}

// ---------------------------------------------------------------------------
// Launch
// ---------------------------------------------------------------------------
extern "C" void kernel_launch(void* const* d_in, const int* in_sizes, int n_in,
                              void* d_out, int out_size) {
    int i_node = -1, i_army = -1, i_edges = -1, i_W1 = -1, i_b1 = -1, i_W2 = -1,
        i_b2 = -1, i_A1 = -1, i_a1 = -1, i_A2 = -1, i_a2 = -1;
    for (int i = 0; i < n_in; i++) {
        switch (in_sizes[i]) {
            case 67108864: i_node = i; break;
            case 262144:   i_army = i; break;
            case 1048576:  i_edges = i; break;
            case 131072:   i_W1 = i; break;
            case 65536:    i_A1 = i; break;
            case 8192:     i_A2 = i; break;
            case 128:      i_a1 = i; break;
            case 64:       i_a2 = i; break;
            case 1:        i_b2 = i; break;
            case 256:      if (i_b1 < 0) i_b1 = i; else i_W2 = i; break;
            default: break;
        }
    }

    const float* node  = (const float*)d_in[i_node];
    const float* army  = (const float*)d_in[i_army];
    const int*   edges = (const int*)  d_in[i_edges];

    float* out_edge = (float*)d_out;
    float* out_army = (float*)d_out + NEDGE;

    cudaFuncSetAttribute(gemm_kernel, cudaFuncAttributeMaxDynamicSharedMemorySize, GEMM_SMEM);

    prep_a_kernel<<<(MROWS * 64 + 255) / 256, 256>>>(node);
    prep_w_kernel<<<(PCOLS * 256 + 255) / 256, 256>>>((const float*)d_in[i_W1],
                                                      (const float*)d_in[i_A1]);
    prep_a2_kernel<<<16, 256>>>((const float*)d_in[i_A2]);

    dim3 ggrid(PCOLS / 256, MROWS / 128);            // (3, 2048)
    gemm_kernel<<<ggrid, 256, GEMM_SMEM>>>();

    edge_kernel<<<EDGE_GRID, 128>>>(army, edges,
                                    (const float*)d_in[i_b1], (const float*)d_in[i_W2],
                                    (const float*)d_in[i_b2], (const float*)d_in[i_a1],
                                    (const float*)d_in[i_a2],
                                    out_edge, out_army);
}

// round 16
// speedup vs baseline: 1.3288x; 1.3288x over previous
#include <cuda_runtime.h>
#include <cuda_bf16.h>
#include <cuda_fp16.h>
#include <cstdint>

// ---------------- problem constants ----------------
#define Bsz 64
#define Nn  4096
#define Ee  8192
#define MROWS (Bsz * Nn)        // 262144
#define PCOLS 768               // [W1top(256) | W1bot(256) | A1top(128) | A1bot(128)]
#define KDIM  256
#define NEDGE (Bsz * Ee)        // 524288

// ---------------- scratch (__device__ globals; no allocs allowed) ----------
__device__ __align__(16) float    g_P[(size_t)MROWS * PCOLS];   // partials fp32 (805 MB)
__device__ __align__(16) __half   g_Ahf[(size_t)MROWS * 256];   // fp16(node) (134 MB)
__device__ __align__(16) __half   g_B2[(size_t)PCOLS * 256];    // [n][k] = fp16(Wcat[k][n])
__device__ __align__(16) uint32_t g_A2Th[64 * 64];              // A2^T hi (bf16 pairs)
__device__ __align__(16) uint32_t g_A2Tl[64 * 64];              // A2^T lo

// ---------------- helpers ----------------
__device__ __forceinline__ uint32_t smem_u32(const void* p) {
    uint32_t a;
    asm("{ .reg .u64 t; cvta.to.shared.u64 t, %1; cvt.u32.u64 %0, t; }" : "=r"(a) : "l"(p));
    return a;
}
__device__ __forceinline__ void cp16(uint32_t dst, const void* src) {
    asm volatile("cp.async.cg.shared.global [%0], [%1], 16;" :: "r"(dst), "l"(src));
}
#define CP_COMMIT() asm volatile("cp.async.commit_group;" ::: "memory")
#define CP_WAIT(n)  asm volatile("cp.async.wait_group %0;" :: "n"(n) : "memory")

__device__ __forceinline__ void mma_f16(float* c,
    uint32_t a0, uint32_t a1, uint32_t a2, uint32_t a3, uint32_t b0, uint32_t b1) {
    asm volatile(
        "mma.sync.aligned.m16n8k16.row.col.f32.f16.f16.f32 "
        "{%0,%1,%2,%3}, {%4,%5,%6,%7}, {%8,%9}, {%0,%1,%2,%3};"
        : "+f"(c[0]), "+f"(c[1]), "+f"(c[2]), "+f"(c[3])
        : "r"(a0), "r"(a1), "r"(a2), "r"(a3), "r"(b0), "r"(b1));
}
__device__ __forceinline__ void mma_bf16(float* c,
    uint32_t a0, uint32_t a1, uint32_t a2, uint32_t a3, uint32_t b0, uint32_t b1) {
    asm volatile(
        "mma.sync.aligned.m16n8k16.row.col.f32.bf16.bf16.f32 "
        "{%0,%1,%2,%3}, {%4,%5,%6,%7}, {%8,%9}, {%0,%1,%2,%3};"
        : "+f"(c[0]), "+f"(c[1]), "+f"(c[2]), "+f"(c[3])
        : "r"(a0), "r"(a1), "r"(a2), "r"(a3), "r"(b0), "r"(b1));
}
__device__ __forceinline__ void ldsm_x4(uint32_t* r, uint32_t addr) {
    asm volatile("ldmatrix.sync.aligned.m8n8.x4.shared.b16 {%0,%1,%2,%3}, [%4];"
        : "=r"(r[0]), "=r"(r[1]), "=r"(r[2]), "=r"(r[3]) : "r"(addr));
}
__device__ __forceinline__ uint32_t pack_bf16(float lo, float hi) {
    __nv_bfloat162 t = __floats2bfloat162_rn(lo, hi);
    return *reinterpret_cast<uint32_t*>(&t);
}

// ---------------------------------------------------------------------------
// prep_a: fp16(node), hi only.
// ---------------------------------------------------------------------------
__global__ __launch_bounds__(256) void prep_a_kernel(const float* __restrict__ node) {
    int i = blockIdx.x * blockDim.x + threadIdx.x;
    if (i >= MROWS * 64) return;
    int m  = i >> 6;
    int kq = (i & 63) * 4;
    float4 v = *reinterpret_cast<const float4*>(node + (size_t)m * 256 + kq);
    __half h[4];
    h[0] = __float2half_rn(v.x);
    h[1] = __float2half_rn(v.y);
    h[2] = __float2half_rn(v.z);
    h[3] = __float2half_rn(v.w);
    *reinterpret_cast<uint2*>(&g_Ahf[(size_t)m * 256 + kq]) = *reinterpret_cast<uint2*>(h);
}

// ---------------------------------------------------------------------------
// prep_w: g_B2[n][k] = fp16(Wcat[k][n])
// ---------------------------------------------------------------------------
__global__ __launch_bounds__(256) void prep_w_kernel(const float* __restrict__ W1,
                                                     const float* __restrict__ A1) {
    int i = blockIdx.x * blockDim.x + threadIdx.x;
    if (i >= PCOLS * 256) return;
    int n = i >> 8;
    int k = i & 255;
    float v;
    if (n < 256)        v = W1[k * 256 + n];
    else if (n < 512)   v = W1[(256 + k) * 256 + (n - 256)];
    else if (n < 640)   v = A1[k * 128 + (n - 512)];
    else                v = A1[(256 + k) * 128 + (n - 640)];
    g_B2[i] = __float2half_rn(v);
}

// ---------------------------------------------------------------------------
// prep_a2: A2^T hi/lo bf16 u32-packed fragments (edge matvec).
// ---------------------------------------------------------------------------
__global__ __launch_bounds__(256) void prep_a2_kernel(const float* __restrict__ A2) {
    int i = blockIdx.x * blockDim.x + threadIdx.x;
    if (i >= 64 * 64) return;
    int n  = i >> 6;
    int kk = i & 63;
    float v0 = A2[(2 * kk)     * 64 + n];
    float v1 = A2[(2 * kk + 1) * 64 + n];
    float h0 = __bfloat162float(__float2bfloat16_rn(v0));
    float h1 = __bfloat162float(__float2bfloat16_rn(v1));
    g_A2Th[i] = pack_bf16(h0, h1);
    g_A2Tl[i] = pack_bf16(v0 - h0, v1 - h1);
}

// ---------------------------------------------------------------------------
// GEMM (R14 shape, 1-term): g_P = Ah @ Bh (fp16, f32 acc), K = 256.
// 128x128 tile, BK=64 (4 iters), 3-stage cp.async pipeline, ldmatrix x4 A+B,
// 2 CTAs/SM.
// ---------------------------------------------------------------------------
#define BK 64
#define AST 72                    // smem row stride in halves
#define STG_H (128 * AST)
#define STAGE_B (2 * STG_H * 2)   // 36864
#define GEMM_SMEM (3 * STAGE_B)   // 110592
#define KITERS 4

__global__ __launch_bounds__(256, 2) void gemm_kernel() {
    extern __shared__ __align__(16) __half dyn[];
    const uint32_t sb = smem_u32(dyn);

    const int tid  = threadIdx.x;
    const int wid  = tid >> 5, lane = tid & 31;
    const int g    = lane >> 2, tig = lane & 3;
    const int warp_m = (wid >> 2) * 64;
    const int warp_n = (wid & 3) * 32;
    const int n0 = blockIdx.x * 128;
    const int m0 = blockIdx.y * 128;

    float acc[4][4][4];
    #pragma unroll
    for (int i = 0; i < 4; i++)
        #pragma unroll
        for (int j = 0; j < 4; j++)
            #pragma unroll
            for (int q = 0; q < 4; q++) acc[i][j][q] = 0.0f;

    auto load_stage = [&](int ks, int buf) {
        const int k0 = ks * BK;
        const uint32_t da = sb + (uint32_t)buf * STAGE_B;
        const uint32_t db = da + STG_H * 2;
        #pragma unroll
        for (int h = 0; h < 4; h++) {
            int id = tid + h * 256;
            int r  = id >> 3, p = id & 7;
            cp16(da + (uint32_t)(r * AST + p * 8) * 2,
                 &g_Ahf[(size_t)(m0 + r) * 256 + k0 + p * 8]);
            cp16(db + (uint32_t)(r * AST + p * 8) * 2,
                 &g_B2[(size_t)(n0 + r) * 256 + k0 + p * 8]);
        }
    };

    const int a_row  = lane & 15;
    const int a_k8   = ((lane >> 4) & 1) * 8;
    const int b_rowp = (lane & 7) + ((lane >> 4) & 1) * 8;
    const int b_k8p  = ((lane >> 3) & 1) * 8;

    load_stage(0, 0); CP_COMMIT();
    load_stage(1, 1); CP_COMMIT();

    for (int ks = 0; ks < KITERS; ks++) {
        if (ks < KITERS - 2) { CP_WAIT(1); } else { CP_WAIT(0); }
        __syncthreads();

        const uint32_t aB = sb + (uint32_t)(ks % 3) * STAGE_B;
        const uint32_t bB = aB + STG_H * 2;

        #pragma unroll
        for (int ksel = 0; ksel < 4; ksel++) {
            uint32_t a[4][4], b[4][2];
            #pragma unroll
            for (int mi = 0; mi < 4; mi++) {
                int row = warp_m + mi * 16 + a_row;
                ldsm_x4(a[mi], aB + (uint32_t)(row * AST + ksel * 16 + a_k8) * 2);
            }
            #pragma unroll
            for (int njp = 0; njp < 2; njp++) {
                int row = warp_n + njp * 16 + b_rowp;
                uint32_t r4[4];
                ldsm_x4(r4, bB + (uint32_t)(row * AST + ksel * 16 + b_k8p) * 2);
                b[2 * njp][0]     = r4[0]; b[2 * njp][1]     = r4[1];
                b[2 * njp + 1][0] = r4[2]; b[2 * njp + 1][1] = r4[3];
            }
            #pragma unroll
            for (int mi = 0; mi < 4; mi++)
                #pragma unroll
                for (int nj = 0; nj < 4; nj++)
                    mma_f16(acc[mi][nj], a[mi][0], a[mi][1], a[mi][2], a[mi][3],
                            b[nj][0], b[nj][1]);
        }

        if (ks + 2 < KITERS) { load_stage(ks + 2, (ks + 2) % 3); CP_COMMIT(); }
    }

    #pragma unroll
    for (int mi = 0; mi < 4; mi++) {
        #pragma unroll
        for (int nj = 0; nj < 4; nj++) {
            int row = m0 + warp_m + mi * 16 + g;
            int col = n0 + warp_n + nj * 8 + 2 * tig;
            *reinterpret_cast<float2*>(&g_P[(size_t)row * PCOLS + col]) =
                make_float2(acc[mi][nj][0], acc[mi][nj][1]);
            *reinterpret_cast<float2*>(&g_P[(size_t)(row + 8) * PCOLS + col]) =
                make_float2(acc[mi][nj][2], acc[mi][nj][3]);
        }
    }
}

// ---------------------------------------------------------------------------
// Edge kernel (R14 best, unchanged): warp-batched 16 edges/tile.
// ---------------------------------------------------------------------------
#define EW 4
#define NTILES (NEDGE / 16)      // 32768
#define EDGE_GRID 1184

__global__ __launch_bounds__(128) void edge_kernel(
    const float* __restrict__ army, const int* __restrict__ edges,
    const float* __restrict__ b1, const float* __restrict__ W2, const float* __restrict__ b2,
    const float* __restrict__ a1, const float* __restrict__ a2,
    float* __restrict__ out_edge, float* __restrict__ out_army)
{
    __shared__ uint32_t stg_h[EW][16 * 64];
    __shared__ uint32_t stg_l[EW][16 * 64];
    __shared__ float b1s[256], W2s[256], a1s[128];
    __shared__ float srcAs[EW][16];

    const int tid = threadIdx.x, w = tid >> 5, lane = tid & 31;
    const int grp = lane >> 2, tig = lane & 3;

    b1s[tid] = b1[tid];       b1s[tid + 128] = b1[tid + 128];
    W2s[tid] = W2[tid];       W2s[tid + 128] = W2[tid + 128];
    a1s[tid] = a1[tid];
    const float b2v = b2[0];

    float2 a2g[8];
    #pragma unroll
    for (int nj = 0; nj < 8; nj++) {
        int m = nj * 8 + 2 * tig;
        a2g[nj] = make_float2(a2[m], a2[m + 1]);
    }
    __syncthreads();

    for (int tile = blockIdx.x * EW + w; tile < NTILES; tile += EDGE_GRID * EW) {
        const int e0 = tile * 16;

        #pragma unroll 2
        for (int e = 0; e < 16; e++) {
            const int eidx = e0 + e;
            const int b = eidx >> 13;
            const int src = edges[2 * eidx], tgt = edges[2 * eidx + 1];
            const int sc = min(max(src, 0), Nn - 1);
            const int tc = min(max(tgt, 0), Nn - 1);
            const float* Ps = g_P + ((size_t)(b << 12) + sc) * PCOLS;
            const float* Pt = g_P + ((size_t)(b << 12) + tc) * PCOLS;

            float ep = 0.0f;
            #pragma unroll
            for (int q = 0; q < 2; q++) {
                int f = lane + 32 * q;
                float4 ps = *reinterpret_cast<const float4*>(Ps + 4 * f);
                float4 pt = *reinterpret_cast<const float4*>(Pt + 256 + 4 * f);
                float4 bb = *reinterpret_cast<const float4*>(b1s + 4 * f);
                float4 ww = *reinterpret_cast<const float4*>(W2s + 4 * f);
                ep += fmaxf(ps.x + pt.x + bb.x, 0.0f) * ww.x;
                ep += fmaxf(ps.y + pt.y + bb.y, 0.0f) * ww.y;
                ep += fmaxf(ps.z + pt.z + bb.z, 0.0f) * ww.z;
                ep += fmaxf(ps.w + pt.w + bb.w, 0.0f) * ww.w;
            }
            #pragma unroll
            for (int o = 16; o; o >>= 1) ep += __shfl_xor_sync(0xffffffffu, ep, o);

            {
                float4 ps = *reinterpret_cast<const float4*>(Ps + 512 + 4 * lane);
                float4 pt = *reinterpret_cast<const float4*>(Pt + 640 + 4 * lane);
                float4 aa = *reinterpret_cast<const float4*>(a1s + 4 * lane);
                float g0 = fmaxf(ps.x + pt.x + aa.x, 0.0f);
                float g1 = fmaxf(ps.y + pt.y + aa.y, 0.0f);
                float g2 = fmaxf(ps.z + pt.z + aa.z, 0.0f);
                float g3 = fmaxf(ps.w + pt.w + aa.w, 0.0f);
                float h0 = __bfloat162float(__float2bfloat16_rn(g0));
                float h1 = __bfloat162float(__float2bfloat16_rn(g1));
                float h2 = __bfloat162float(__float2bfloat16_rn(g2));
                float h3 = __bfloat162float(__float2bfloat16_rn(g3));
                const uint32_t sw = 4u * (e & 7);
                const uint32_t o0 = (uint32_t)(e * 64) + ((2u * lane)     ^ sw);
                const uint32_t o1 = (uint32_t)(e * 64) + ((2u * lane + 1) ^ sw);
                stg_h[w][o0] = pack_bf16(h0, h1);
                stg_h[w][o1] = pack_bf16(h2, h3);
                stg_l[w][o0] = pack_bf16(g0 - h0, g1 - h1);
                stg_l[w][o1] = pack_bf16(g2 - h2, g3 - h3);
            }

            const float srcA = army[(b << 12) + sc];
            const float tgtA = army[(b << 12) + tc];
            if (lane == 0) {
                float el = ep + b2v;
                bool valid = (src >= 0) && (tgt >= 0);
                if (valid && ((srcA <= 2.0f) || (tgtA >= 3.0f * srcA))) el -= 1.0f;
                if (valid && (src == tgt))                              el -= 100.0f;
                out_edge[eidx] = el;
                srcAs[w][e] = srcA;
            }
        }
        __syncwarp();

        float acc[8][4];
        #pragma unroll
        for (int nj = 0; nj < 8; nj++)
            #pragma unroll
            for (int q = 0; q < 4; q++) acc[nj][q] = 0.0f;

        const uint32_t swg = 4u * grp;
        #pragma unroll
        for (int ks = 0; ks < 8; ks++) {
            const uint32_t kb = 8u * ks;
            uint32_t ah0 = stg_h[w][grp * 64       + ((kb + tig)     ^ swg)];
            uint32_t ah1 = stg_h[w][(grp + 8) * 64 + ((kb + tig)     ^ swg)];
            uint32_t ah2 = stg_h[w][grp * 64       + ((kb + 4 + tig) ^ swg)];
            uint32_t ah3 = stg_h[w][(grp + 8) * 64 + ((kb + 4 + tig) ^ swg)];
            uint32_t al0 = stg_l[w][grp * 64       + ((kb + tig)     ^ swg)];
            uint32_t al1 = stg_l[w][(grp + 8) * 64 + ((kb + tig)     ^ swg)];
            uint32_t al2 = stg_l[w][grp * 64       + ((kb + 4 + tig) ^ swg)];
            uint32_t al3 = stg_l[w][(grp + 8) * 64 + ((kb + 4 + tig) ^ swg)];
            #pragma unroll
            for (int nj = 0; nj < 8; nj++) {
                const int bi = (nj * 8 + grp) * 64 + kb + tig;
                uint32_t bh0 = g_A2Th[bi], bh1 = g_A2Th[bi + 4];
                uint32_t bl0 = g_A2Tl[bi], bl1 = g_A2Tl[bi + 4];
                mma_bf16(acc[nj], ah0, ah1, ah2, ah3, bh0, bh1);
                mma_bf16(acc[nj], ah0, ah1, ah2, ah3, bl0, bl1);
                mma_bf16(acc[nj], al0, al1, al2, al3, bh0, bh1);
            }
        }

        const float mS0 = srcAs[w][grp] - 1.0f;
        const float mS1 = srcAs[w][grp + 8] - 1.0f;
        float* o0 = out_army + (size_t)(e0 + grp) * 64;
        float* o1 = out_army + (size_t)(e0 + grp + 8) * 64;
        #pragma unroll
        for (int nj = 0; nj < 8; nj++) {
            const int m = nj * 8 + 2 * tig;
            const float fm0 = (float)m, fm1 = (float)(m + 1);
            float v0 = (fm0 <= mS0) ? acc[nj][0] + a2g[nj].x : -1e9f;
            float v1 = (fm1 <= mS0) ? acc[nj][1] + a2g[nj].y : -1e9f;
            float v2 = (fm0 <= mS1) ? acc[nj][2] + a2g[nj].x : -1e9f;
            float v3 = (fm1 <= mS1) ? acc[nj][3] + a2g[nj].y : -1e9f;
            *reinterpret_cast<float2*>(o0 + m) = make_float2(v0, v1);
            *reinterpret_cast<float2*>(o1 + m) = make_float2(v2, v3);
        }
        __syncwarp();
    }
}

// ---------------------------------------------------------------------------
// Launch
// ---------------------------------------------------------------------------
extern "C" void kernel_launch(void* const* d_in, const int* in_sizes, int n_in,
                              void* d_out, int out_size) {
    int i_node = -1, i_army = -1, i_edges = -1, i_W1 = -1, i_b1 = -1, i_W2 = -1,
        i_b2 = -1, i_A1 = -1, i_a1 = -1, i_A2 = -1, i_a2 = -1;
    for (int i = 0; i < n_in; i++) {
        switch (in_sizes[i]) {
            case 67108864: i_node = i; break;
            case 262144:   i_army = i; break;
            case 1048576:  i_edges = i; break;
            case 131072:   i_W1 = i; break;
            case 65536:    i_A1 = i; break;
            case 8192:     i_A2 = i; break;
            case 128:      i_a1 = i; break;
            case 64:       i_a2 = i; break;
            case 1:        i_b2 = i; break;
            case 256:      if (i_b1 < 0) i_b1 = i; else i_W2 = i; break;
            default: break;
        }
    }

    const float* node  = (const float*)d_in[i_node];
    const float* army  = (const float*)d_in[i_army];
    const int*   edges = (const int*)  d_in[i_edges];

    float* out_edge = (float*)d_out;
    float* out_army = (float*)d_out + NEDGE;

    cudaFuncSetAttribute(gemm_kernel, cudaFuncAttributeMaxDynamicSharedMemorySize, GEMM_SMEM);

    prep_a_kernel<<<(MROWS * 64 + 255) / 256, 256>>>(node);
    prep_w_kernel<<<(PCOLS * 256 + 255) / 256, 256>>>((const float*)d_in[i_W1],
                                                      (const float*)d_in[i_A1]);
    prep_a2_kernel<<<16, 256>>>((const float*)d_in[i_A2]);

    dim3 ggrid(PCOLS / 128, MROWS / 128);            // (6, 2048)
    gemm_kernel<<<ggrid, 256, GEMM_SMEM>>>();

    edge_kernel<<<EDGE_GRID, 128>>>(army, edges,
                                    (const float*)d_in[i_b1], (const float*)d_in[i_W2],
                                    (const float*)d_in[i_b2], (const float*)d_in[i_a1],
                                    (const float*)d_in[i_a2],
                                    out_edge, out_army);
}

// round 17
// speedup vs baseline: 1.4809x; 1.1145x over previous
#include <cuda_runtime.h>
#include <cuda_bf16.h>
#include <cuda_fp16.h>
#include <cstdint>

// ---------------- problem constants ----------------
#define Bsz 64
#define Nn  4096
#define Ee  8192
#define MROWS (Bsz * Nn)        // 262144
#define PCOLS 768               // [W1top(256) | W1bot(256) | A1top(128) | A1bot(128)]
#define KDIM  256
#define NEDGE (Bsz * Ee)        // 524288

// ---------------- scratch (__device__ globals; no allocs allowed) ----------
__device__ __align__(16) float    g_P[(size_t)MROWS * PCOLS];   // partials fp32 (805 MB)
__device__ __align__(16) __half   g_Ahf[(size_t)MROWS * 256];   // fp16(node) (134 MB)
__device__ __align__(16) __half   g_B2[(size_t)PCOLS * 256];    // [n][k] = fp16(Wcat[k][n])
__device__ __align__(16) uint32_t g_A2T[64 * 64];               // A2^T fp16 pairs

// ---------------- helpers ----------------
__device__ __forceinline__ uint32_t smem_u32(const void* p) {
    uint32_t a;
    asm("{ .reg .u64 t; cvta.to.shared.u64 t, %1; cvt.u32.u64 %0, t; }" : "=r"(a) : "l"(p));
    return a;
}
__device__ __forceinline__ void cp16(uint32_t dst, const void* src) {
    asm volatile("cp.async.cg.shared.global [%0], [%1], 16;" :: "r"(dst), "l"(src));
}
#define CP_COMMIT() asm volatile("cp.async.commit_group;" ::: "memory")
#define CP_WAIT(n)  asm volatile("cp.async.wait_group %0;" :: "n"(n) : "memory")

__device__ __forceinline__ void mma_f16(float* c,
    uint32_t a0, uint32_t a1, uint32_t a2, uint32_t a3, uint32_t b0, uint32_t b1) {
    asm volatile(
        "mma.sync.aligned.m16n8k16.row.col.f32.f16.f16.f32 "
        "{%0,%1,%2,%3}, {%4,%5,%6,%7}, {%8,%9}, {%0,%1,%2,%3};"
        : "+f"(c[0]), "+f"(c[1]), "+f"(c[2]), "+f"(c[3])
        : "r"(a0), "r"(a1), "r"(a2), "r"(a3), "r"(b0), "r"(b1));
}
__device__ __forceinline__ void ldsm_x4(uint32_t* r, uint32_t addr) {
    asm volatile("ldmatrix.sync.aligned.m8n8.x4.shared.b16 {%0,%1,%2,%3}, [%4];"
        : "=r"(r[0]), "=r"(r[1]), "=r"(r[2]), "=r"(r[3]) : "r"(addr));
}
__device__ __forceinline__ uint32_t pack_f16(float lo, float hi) {
    __half2 t = __floats2half2_rn(lo, hi);
    return *reinterpret_cast<uint32_t*>(&t);
}

// ---------------------------------------------------------------------------
// prep_a: fp16(node).
// ---------------------------------------------------------------------------
__global__ __launch_bounds__(256) void prep_a_kernel(const float* __restrict__ node) {
    int i = blockIdx.x * blockDim.x + threadIdx.x;
    if (i >= MROWS * 64) return;
    int m  = i >> 6;
    int kq = (i & 63) * 4;
    float4 v = *reinterpret_cast<const float4*>(node + (size_t)m * 256 + kq);
    __half h[4];
    h[0] = __float2half_rn(v.x);
    h[1] = __float2half_rn(v.y);
    h[2] = __float2half_rn(v.z);
    h[3] = __float2half_rn(v.w);
    *reinterpret_cast<uint2*>(&g_Ahf[(size_t)m * 256 + kq]) = *reinterpret_cast<uint2*>(h);
}

// ---------------------------------------------------------------------------
// prep_w: g_B2[n][k] = fp16(Wcat[k][n])
// ---------------------------------------------------------------------------
__global__ __launch_bounds__(256) void prep_w_kernel(const float* __restrict__ W1,
                                                     const float* __restrict__ A1) {
    int i = blockIdx.x * blockDim.x + threadIdx.x;
    if (i >= PCOLS * 256) return;
    int n = i >> 8;
    int k = i & 255;
    float v;
    if (n < 256)        v = W1[k * 256 + n];
    else if (n < 512)   v = W1[(256 + k) * 256 + (n - 256)];
    else if (n < 640)   v = A1[k * 128 + (n - 512)];
    else                v = A1[(256 + k) * 128 + (n - 640)];
    g_B2[i] = __float2half_rn(v);
}

// ---------------------------------------------------------------------------
// prep_a2: A2^T fp16 u32-packed fragments (edge matvec, 1-term).
// ---------------------------------------------------------------------------
__global__ __launch_bounds__(256) void prep_a2_kernel(const float* __restrict__ A2) {
    int i = blockIdx.x * blockDim.x + threadIdx.x;
    if (i >= 64 * 64) return;
    int n  = i >> 6;
    int kk = i & 63;
    g_A2T[i] = pack_f16(A2[(2 * kk) * 64 + n], A2[(2 * kk + 1) * 64 + n]);
}

// ---------------------------------------------------------------------------
// GEMM (R16 measured-best, unchanged): g_P = Ah @ Bh (fp16, f32 acc), K=256.
// 128x128 tile, BK=64 (4 iters), 3-stage cp.async pipeline, ldsm x4, 2 CTA/SM.
// ---------------------------------------------------------------------------
#define BK 64
#define AST 72                    // smem row stride in halves
#define STG_H (128 * AST)
#define STAGE_B (2 * STG_H * 2)   // 36864
#define GEMM_SMEM (3 * STAGE_B)   // 110592
#define KITERS 4

__global__ __launch_bounds__(256, 2) void gemm_kernel() {
    extern __shared__ __align__(16) __half dyn[];
    const uint32_t sb = smem_u32(dyn);

    const int tid  = threadIdx.x;
    const int wid  = tid >> 5, lane = tid & 31;
    const int g    = lane >> 2, tig = lane & 3;
    const int warp_m = (wid >> 2) * 64;
    const int warp_n = (wid & 3) * 32;
    const int n0 = blockIdx.x * 128;
    const int m0 = blockIdx.y * 128;

    float acc[4][4][4];
    #pragma unroll
    for (int i = 0; i < 4; i++)
        #pragma unroll
        for (int j = 0; j < 4; j++)
            #pragma unroll
            for (int q = 0; q < 4; q++) acc[i][j][q] = 0.0f;

    auto load_stage = [&](int ks, int buf) {
        const int k0 = ks * BK;
        const uint32_t da = sb + (uint32_t)buf * STAGE_B;
        const uint32_t db = da + STG_H * 2;
        #pragma unroll
        for (int h = 0; h < 4; h++) {
            int id = tid + h * 256;
            int r  = id >> 3, p = id & 7;
            cp16(da + (uint32_t)(r * AST + p * 8) * 2,
                 &g_Ahf[(size_t)(m0 + r) * 256 + k0 + p * 8]);
            cp16(db + (uint32_t)(r * AST + p * 8) * 2,
                 &g_B2[(size_t)(n0 + r) * 256 + k0 + p * 8]);
        }
    };

    const int a_row  = lane & 15;
    const int a_k8   = ((lane >> 4) & 1) * 8;
    const int b_rowp = (lane & 7) + ((lane >> 4) & 1) * 8;
    const int b_k8p  = ((lane >> 3) & 1) * 8;

    load_stage(0, 0); CP_COMMIT();
    load_stage(1, 1); CP_COMMIT();

    for (int ks = 0; ks < KITERS; ks++) {
        if (ks < KITERS - 2) { CP_WAIT(1); } else { CP_WAIT(0); }
        __syncthreads();

        const uint32_t aB = sb + (uint32_t)(ks % 3) * STAGE_B;
        const uint32_t bB = aB + STG_H * 2;

        #pragma unroll
        for (int ksel = 0; ksel < 4; ksel++) {
            uint32_t a[4][4], b[4][2];
            #pragma unroll
            for (int mi = 0; mi < 4; mi++) {
                int row = warp_m + mi * 16 + a_row;
                ldsm_x4(a[mi], aB + (uint32_t)(row * AST + ksel * 16 + a_k8) * 2);
            }
            #pragma unroll
            for (int njp = 0; njp < 2; njp++) {
                int row = warp_n + njp * 16 + b_rowp;
                uint32_t r4[4];
                ldsm_x4(r4, bB + (uint32_t)(row * AST + ksel * 16 + b_k8p) * 2);
                b[2 * njp][0]     = r4[0]; b[2 * njp][1]     = r4[1];
                b[2 * njp + 1][0] = r4[2]; b[2 * njp + 1][1] = r4[3];
            }
            #pragma unroll
            for (int mi = 0; mi < 4; mi++)
                #pragma unroll
                for (int nj = 0; nj < 4; nj++)
                    mma_f16(acc[mi][nj], a[mi][0], a[mi][1], a[mi][2], a[mi][3],
                            b[nj][0], b[nj][1]);
        }

        if (ks + 2 < KITERS) { load_stage(ks + 2, (ks + 2) % 3); CP_COMMIT(); }
    }

    #pragma unroll
    for (int mi = 0; mi < 4; mi++) {
        #pragma unroll
        for (int nj = 0; nj < 4; nj++) {
            int row = m0 + warp_m + mi * 16 + g;
            int col = n0 + warp_n + nj * 8 + 2 * tig;
            *reinterpret_cast<float2*>(&g_P[(size_t)row * PCOLS + col]) =
                make_float2(acc[mi][nj][0], acc[mi][nj][1]);
            *reinterpret_cast<float2*>(&g_P[(size_t)(row + 8) * PCOLS + col]) =
                make_float2(acc[mi][nj][2], acc[mi][nj][3]);
        }
    }
}

// ---------------------------------------------------------------------------
// Edge kernel: warp-batched 16 edges/tile. Phase-2 matvec now fp16 1-term
// (staging halved to 16KB/block -> 8 blocks/SM fit in smem; 64 MMA/tile).
// ---------------------------------------------------------------------------
#define EW 4
#define NTILES (NEDGE / 16)      // 32768
#define EDGE_GRID 1184

__global__ __launch_bounds__(128) void edge_kernel(
    const float* __restrict__ army, const int* __restrict__ edges,
    const float* __restrict__ b1, const float* __restrict__ W2, const float* __restrict__ b2,
    const float* __restrict__ a1, const float* __restrict__ a2,
    float* __restrict__ out_edge, float* __restrict__ out_army)
{
    __shared__ uint32_t stg[EW][16 * 64];      // fp16 g staging (swizzled)
    __shared__ float b1s[256], W2s[256], a1s[128];
    __shared__ float srcAs[EW][16];

    const int tid = threadIdx.x, w = tid >> 5, lane = tid & 31;
    const int grp = lane >> 2, tig = lane & 3;

    b1s[tid] = b1[tid];       b1s[tid + 128] = b1[tid + 128];
    W2s[tid] = W2[tid];       W2s[tid + 128] = W2[tid + 128];
    a1s[tid] = a1[tid];
    const float b2v = b2[0];

    float2 a2g[8];
    #pragma unroll
    for (int nj = 0; nj < 8; nj++) {
        int m = nj * 8 + 2 * tig;
        a2g[nj] = make_float2(a2[m], a2[m + 1]);
    }
    __syncthreads();

    for (int tile = blockIdx.x * EW + w; tile < NTILES; tile += EDGE_GRID * EW) {
        const int e0 = tile * 16;

        #pragma unroll 2
        for (int e = 0; e < 16; e++) {
            const int eidx = e0 + e;
            const int b = eidx >> 13;
            const int src = edges[2 * eidx], tgt = edges[2 * eidx + 1];
            const int sc = min(max(src, 0), Nn - 1);
            const int tc = min(max(tgt, 0), Nn - 1);
            const float* Ps = g_P + ((size_t)(b << 12) + sc) * PCOLS;
            const float* Pt = g_P + ((size_t)(b << 12) + tc) * PCOLS;

            float ep = 0.0f;
            #pragma unroll
            for (int q = 0; q < 2; q++) {
                int f = lane + 32 * q;
                float4 ps = *reinterpret_cast<const float4*>(Ps + 4 * f);
                float4 pt = *reinterpret_cast<const float4*>(Pt + 256 + 4 * f);
                float4 bb = *reinterpret_cast<const float4*>(b1s + 4 * f);
                float4 ww = *reinterpret_cast<const float4*>(W2s + 4 * f);
                ep += fmaxf(ps.x + pt.x + bb.x, 0.0f) * ww.x;
                ep += fmaxf(ps.y + pt.y + bb.y, 0.0f) * ww.y;
                ep += fmaxf(ps.z + pt.z + bb.z, 0.0f) * ww.z;
                ep += fmaxf(ps.w + pt.w + bb.w, 0.0f) * ww.w;
            }
            #pragma unroll
            for (int o = 16; o; o >>= 1) ep += __shfl_xor_sync(0xffffffffu, ep, o);

            {
                float4 ps = *reinterpret_cast<const float4*>(Ps + 512 + 4 * lane);
                float4 pt = *reinterpret_cast<const float4*>(Pt + 640 + 4 * lane);
                float4 aa = *reinterpret_cast<const float4*>(a1s + 4 * lane);
                float g0 = fmaxf(ps.x + pt.x + aa.x, 0.0f);
                float g1 = fmaxf(ps.y + pt.y + aa.y, 0.0f);
                float g2 = fmaxf(ps.z + pt.z + aa.z, 0.0f);
                float g3 = fmaxf(ps.w + pt.w + aa.w, 0.0f);
                const uint32_t sw = 4u * (e & 7);
                const uint32_t o0 = (uint32_t)(e * 64) + ((2u * lane)     ^ sw);
                const uint32_t o1 = (uint32_t)(e * 64) + ((2u * lane + 1) ^ sw);
                stg[w][o0] = pack_f16(g0, g1);
                stg[w][o1] = pack_f16(g2, g3);
            }

            const float srcA = army[(b << 12) + sc];
            const float tgtA = army[(b << 12) + tc];
            if (lane == 0) {
                float el = ep + b2v;
                bool valid = (src >= 0) && (tgt >= 0);
                if (valid && ((srcA <= 2.0f) || (tgtA >= 3.0f * srcA))) el -= 1.0f;
                if (valid && (src == tgt))                              el -= 100.0f;
                out_edge[eidx] = el;
                srcAs[w][e] = srcA;
            }
        }
        __syncwarp();

        // phase 2: [16,128] @ [128,64] via fp16 mma, 1-term
        float acc[8][4];
        #pragma unroll
        for (int nj = 0; nj < 8; nj++)
            #pragma unroll
            for (int q = 0; q < 4; q++) acc[nj][q] = 0.0f;

        const uint32_t swg = 4u * grp;
        #pragma unroll
        for (int ks = 0; ks < 8; ks++) {
            const uint32_t kb = 8u * ks;
            uint32_t a0 = stg[w][grp * 64       + ((kb + tig)     ^ swg)];
            uint32_t a1r = stg[w][(grp + 8) * 64 + ((kb + tig)     ^ swg)];
            uint32_t a2r = stg[w][grp * 64       + ((kb + 4 + tig) ^ swg)];
            uint32_t a3 = stg[w][(grp + 8) * 64 + ((kb + 4 + tig) ^ swg)];
            #pragma unroll
            for (int nj = 0; nj < 8; nj++) {
                const int bi = (nj * 8 + grp) * 64 + kb + tig;
                mma_f16(acc[nj], a0, a1r, a2r, a3, g_A2T[bi], g_A2T[bi + 4]);
            }
        }

        const float mS0 = srcAs[w][grp] - 1.0f;
        const float mS1 = srcAs[w][grp + 8] - 1.0f;
        float* o0 = out_army + (size_t)(e0 + grp) * 64;
        float* o1 = out_army + (size_t)(e0 + grp + 8) * 64;
        #pragma unroll
        for (int nj = 0; nj < 8; nj++) {
            const int m = nj * 8 + 2 * tig;
            const float fm0 = (float)m, fm1 = (float)(m + 1);
            float v0 = (fm0 <= mS0) ? acc[nj][0] + a2g[nj].x : -1e9f;
            float v1 = (fm1 <= mS0) ? acc[nj][1] + a2g[nj].y : -1e9f;
            float v2 = (fm0 <= mS1) ? acc[nj][2] + a2g[nj].x : -1e9f;
            float v3 = (fm1 <= mS1) ? acc[nj][3] + a2g[nj].y : -1e9f;
            *reinterpret_cast<float2*>(o0 + m) = make_float2(v0, v1);
            *reinterpret_cast<float2*>(o1 + m) = make_float2(v2, v3);
        }
        __syncwarp();
    }
}

// ---------------------------------------------------------------------------
// Launch
// ---------------------------------------------------------------------------
extern "C" void kernel_launch(void* const* d_in, const int* in_sizes, int n_in,
                              void* d_out, int out_size) {
    int i_node = -1, i_army = -1, i_edges = -1, i_W1 = -1, i_b1 = -1, i_W2 = -1,
        i_b2 = -1, i_A1 = -1, i_a1 = -1, i_A2 = -1, i_a2 = -1;
    for (int i = 0; i < n_in; i++) {
        switch (in_sizes[i]) {
            case 67108864: i_node = i; break;
            case 262144:   i_army = i; break;
            case 1048576:  i_edges = i; break;
            case 131072:   i_W1 = i; break;
            case 65536:    i_A1 = i; break;
            case 8192:     i_A2 = i; break;
            case 128:      i_a1 = i; break;
            case 64:       i_a2 = i; break;
            case 1:        i_b2 = i; break;
            case 256:      if (i_b1 < 0) i_b1 = i; else i_W2 = i; break;
            default: break;
        }
    }

    const float* node  = (const float*)d_in[i_node];
    const float* army  = (const float*)d_in[i_army];
    const int*   edges = (const int*)  d_in[i_edges];

    float* out_edge = (float*)d_out;
    float* out_army = (float*)d_out + NEDGE;

    cudaFuncSetAttribute(gemm_kernel, cudaFuncAttributeMaxDynamicSharedMemorySize, GEMM_SMEM);

    prep_a_kernel<<<(MROWS * 64 + 255) / 256, 256>>>(node);
    prep_w_kernel<<<(PCOLS * 256 + 255) / 256, 256>>>((const float*)d_in[i_W1],
                                                      (const float*)d_in[i_A1]);
    prep_a2_kernel<<<16, 256>>>((const float*)d_in[i_A2]);

    dim3 ggrid(PCOLS / 128, MROWS / 128);            // (6, 2048)
    gemm_kernel<<<ggrid, 256, GEMM_SMEM>>>();

    edge_kernel<<<EDGE_GRID, 128>>>(army, edges,
                                    (const float*)d_in[i_b1], (const float*)d_in[i_W2],
                                    (const float*)d_in[i_b2], (const float*)d_in[i_a1],
                                    (const float*)d_in[i_a2],
                                    out_edge, out_army);
}